// round 5
// baseline (speedup 1.0000x reference)
#include <cuda_runtime.h>
#include <math.h>

#define NN 50000
#define EE 800000
#define HH 128

// ---------------- scratch (static device globals; no allocation) ----------------
__device__ float g_deg[NN];                 // degree, then overwritten with dinv
__device__ int   g_indeg[NN];
__device__ int   g_rowptr[NN + 1];
__device__ int   g_cursor[NN];
__device__ int   g_col[EE];
__device__ float g_wgt[EE];

__device__ float g_h  [(size_t)NN * HH];
__device__ float g_T1 [(size_t)NN * HH];
__device__ float g_T2 [(size_t)NN * HH];
__device__ float g_T3 [(size_t)NN * HH];
__device__ float g_acc[(size_t)NN * HH];

__device__ float g_q1[NN * 3], g_q2[NN * 3], g_q3[NN * 3];
__device__ float g_sum[HH], g_sumsq[HH];

// ---------------- setup kernels ----------------
__global__ void k_zero() {
    int i = blockIdx.x * blockDim.x + threadIdx.x;
    if (i < NN) { g_deg[i] = 0.f; g_indeg[i] = 0; }
    if (i < HH) { g_sum[i] = 0.f; g_sumsq[i] = 0.f; }
}

__global__ void k_degree(const int* __restrict__ ei) {
    int e = blockIdx.x * blockDim.x + threadIdx.x;
    if (e >= EE) return;
    atomicAdd(&g_deg[ei[e]], 1.0f);       // out-degree over src
    atomicAdd(&g_indeg[ei[EE + e]], 1);   // in-degree for CSR-by-dst
}

__global__ void k_dinv() {
    int i = blockIdx.x * blockDim.x + threadIdx.x;
    if (i >= NN) return;
    float d = g_deg[i];
    g_deg[i] = (d > 0.f) ? rsqrtf(d) : 0.f;
}

// single-block exclusive scan of indeg -> rowptr (and cursor copy)
__global__ void k_scan() {
    __shared__ int sh[1024];
    int t = threadIdx.x;
    int carry = 0;
    for (int base = 0; base < NN; base += 1024) {
        int i = base + t;
        int v = (i < NN) ? g_indeg[i] : 0;
        sh[t] = v;
        __syncthreads();
        for (int off = 1; off < 1024; off <<= 1) {
            int add = (t >= off) ? sh[t - off] : 0;
            __syncthreads();
            sh[t] += add;
            __syncthreads();
        }
        int incl = sh[t];
        if (i < NN) {
            int ex = carry + incl - v;
            g_rowptr[i] = ex;
            g_cursor[i] = ex;
        }
        carry += sh[1023];
        __syncthreads();
    }
    if (t == 0) g_rowptr[NN] = carry;
}

__global__ void k_scatter(const int* __restrict__ ei) {
    int e = blockIdx.x * blockDim.x + threadIdx.x;
    if (e >= EE) return;
    int s = ei[e];
    int d = ei[EE + e];
    float w = -g_deg[s] * g_deg[d];   // g_deg holds dinv now
    int pos = atomicAdd(&g_cursor[d], 1);
    g_col[pos] = s;
    g_wgt[pos] = w;
}

// ---------------- propagation: out = scale * (L @ t) + beta * sub ----------------
// H=128, one warp per destination node, float4 per lane, no atomics (CSR).
__global__ void k_prop128(const float* __restrict__ t, const float* __restrict__ sub,
                          float* __restrict__ out, float scale, float beta) {
    int gw = (blockIdx.x * blockDim.x + threadIdx.x) >> 5;
    int lane = threadIdx.x & 31;
    if (gw >= NN) return;
    int beg = g_rowptr[gw], end = g_rowptr[gw + 1];
    float ax = 0.f, ay = 0.f, az = 0.f, aw = 0.f;
    for (int e = beg; e < end; e++) {
        int s = __ldg(&g_col[e]);
        float w = __ldg(&g_wgt[e]);
        float4 v = *(const float4*)&t[(size_t)s * HH + lane * 4];
        ax += w * v.x; ay += w * v.y; az += w * v.z; aw += w * v.w;
    }
    float4 r;
    if (beta != 0.f) {
        float4 sv = *(const float4*)&sub[(size_t)gw * HH + lane * 4];
        r.x = scale * ax + beta * sv.x;
        r.y = scale * ay + beta * sv.y;
        r.z = scale * az + beta * sv.z;
        r.w = scale * aw + beta * sv.w;
    } else {
        r.x = scale * ax; r.y = scale * ay; r.z = scale * az; r.w = scale * aw;
    }
    *(float4*)&out[(size_t)gw * HH + lane * 4] = r;
}

// 3-wide propagation (layer 1 basis), thread per node.
__global__ void k_prop3(const float* __restrict__ t, const float* __restrict__ sub,
                        float* __restrict__ out, float scale, float beta) {
    int i = blockIdx.x * blockDim.x + threadIdx.x;
    if (i >= NN) return;
    int beg = g_rowptr[i], end = g_rowptr[i + 1];
    float a0 = 0.f, a1 = 0.f, a2 = 0.f;
    for (int e = beg; e < end; e++) {
        int s = g_col[e];
        float w = g_wgt[e];
        a0 += w * t[s * 3 + 0];
        a1 += w * t[s * 3 + 1];
        a2 += w * t[s * 3 + 2];
    }
    if (beta != 0.f) {
        out[i * 3 + 0] = scale * a0 + beta * sub[i * 3 + 0];
        out[i * 3 + 1] = scale * a1 + beta * sub[i * 3 + 1];
        out[i * 3 + 2] = scale * a2 + beta * sub[i * 3 + 2];
    } else {
        out[i * 3 + 0] = scale * a0;
        out[i * 3 + 1] = scale * a1;
        out[i * 3 + 2] = scale * a2;
    }
}

// ---------------- layer 1: cheb(3->128) + bias + leaky_relu + stats ----------------
#define L1_ROWS 64
__global__ void k_layer1(const float* __restrict__ x,
                         const float* __restrict__ W1, const float* __restrict__ b1) {
    __shared__ float w[4 * 3 * HH];
    __shared__ float bb[HH];
    for (int i = threadIdx.x; i < 4 * 3 * HH; i += blockDim.x) w[i] = W1[i];
    if (threadIdx.x < HH) bb[threadIdx.x] = b1[threadIdx.x];
    __syncthreads();
    int h = threadIdx.x;  // 128 threads
    int row0 = blockIdx.x * L1_ROWS;
    float s = 0.f, sq = 0.f;
    for (int r = 0; r < L1_ROWS; r++) {
        int i = row0 + r;
        if (i >= NN) break;
        float acc = bb[h];
        #pragma unroll
        for (int c = 0; c < 3; c++) {
            acc += x[i * 3 + c]    * w[(0 * 3 + c) * HH + h];
            acc += g_q1[i * 3 + c] * w[(1 * 3 + c) * HH + h];
            acc += g_q2[i * 3 + c] * w[(2 * 3 + c) * HH + h];
            acc += g_q3[i * 3 + c] * w[(3 * 3 + c) * HH + h];
        }
        float y = (acc > 0.f) ? acc : 0.01f * acc;  // leaky_relu(0.01)
        g_acc[(size_t)i * HH + h] = y;
        s += y; sq += y * y;
    }
    atomicAdd(&g_sum[h], s);
    atomicAdd(&g_sumsq[h], sq);
}

// ---------------- fused 4-term GEMM: acc = act(h@W0 + T1@W1 + T2@W2 + T3@W3 + b) ----
// If bias == nullptr: plain store (no bias, no activation) — layer 4.
#define BM 64
#define BN 128
#define BK 32
__global__ void __launch_bounds__(256, 2)
k_gemm4(const float* __restrict__ T0, const float* __restrict__ T1,
        const float* __restrict__ T2, const float* __restrict__ T3,
        const float* __restrict__ W, float* __restrict__ C,
        const float* __restrict__ bias, float slope) {
    __shared__ float As[BK][BM + 1];
    __shared__ float Bs[BK][BN];
    int row0 = blockIdx.x * BM;
    int tx = threadIdx.x & 15;   // col group (8 cols each)
    int ty = threadIdx.x >> 4;   // row group (4 rows each)
    float acc[4][8];
    #pragma unroll
    for (int i = 0; i < 4; i++)
        #pragma unroll
        for (int j = 0; j < 8; j++) acc[i][j] = 0.f;

    const float* Ts[4] = {T0, T1, T2, T3};
    for (int k = 0; k < 4; k++) {
        const float* T  = Ts[k];
        const float* Wk = W + (size_t)k * HH * HH;
        for (int c0 = 0; c0 < HH; c0 += BK) {
            // A tile: 64 rows x 32 cols (store transposed)
            {
                int r = threadIdx.x >> 3;          // 0..31
                int c = (threadIdx.x & 7) * 4;     // 0..28
                #pragma unroll
                for (int rr = r; rr < BM; rr += 32) {
                    int gi = row0 + rr;
                    float4 v = make_float4(0.f, 0.f, 0.f, 0.f);
                    if (gi < NN) v = *(const float4*)&T[(size_t)gi * HH + c0 + c];
                    As[c + 0][rr] = v.x; As[c + 1][rr] = v.y;
                    As[c + 2][rr] = v.z; As[c + 3][rr] = v.w;
                }
            }
            // B tile: 32 rows x 128 cols
            {
                int c   = threadIdx.x >> 3;
                int col = (threadIdx.x & 7) * 16;
                const float4* src = (const float4*)&Wk[(size_t)(c0 + c) * HH + col];
                float4* dst = (float4*)&Bs[c][col];
                dst[0] = src[0]; dst[1] = src[1]; dst[2] = src[2]; dst[3] = src[3];
            }
            __syncthreads();
            #pragma unroll
            for (int c = 0; c < BK; c++) {
                float a[4], b[8];
                #pragma unroll
                for (int i = 0; i < 4; i++) a[i] = As[c][ty * 4 + i];
                #pragma unroll
                for (int j = 0; j < 8; j++) b[j] = Bs[c][tx * 8 + j];
                #pragma unroll
                for (int i = 0; i < 4; i++)
                    #pragma unroll
                    for (int j = 0; j < 8; j++) acc[i][j] += a[i] * b[j];
            }
            __syncthreads();
        }
    }
    float bv[8];
    if (bias) {
        #pragma unroll
        for (int j = 0; j < 8; j++) bv[j] = bias[tx * 8 + j];
    }
    #pragma unroll
    for (int i = 0; i < 4; i++) {
        int gi = row0 + ty * 4 + i;
        if (gi >= NN) continue;
        if (bias) {
            #pragma unroll
            for (int j = 0; j < 8; j++) {
                float v = acc[i][j] + bv[j];
                acc[i][j] = (v > 0.f) ? v : slope * v;
            }
        }
        float4* dst = (float4*)&C[(size_t)gi * HH + tx * 8];
        dst[0] = make_float4(acc[i][0], acc[i][1], acc[i][2], acc[i][3]);
        dst[1] = make_float4(acc[i][4], acc[i][5], acc[i][6], acc[i][7]);
    }
}

// ---------------- BN-stats over g_acc (read-only; act/bias already applied) -------
#define AS_ROWS 256
__global__ void k_stats() {
    int h = threadIdx.x;  // 128 threads
    int row0 = blockIdx.x * AS_ROWS;
    float s = 0.f, sq = 0.f;
    for (int r = 0; r < AS_ROWS; r++) {
        int i = row0 + r;
        if (i >= NN) break;
        float v = g_acc[(size_t)i * HH + h];
        s += v; sq += v * v;
    }
    atomicAdd(&g_sum[h], s);
    atomicAdd(&g_sumsq[h], sq);
}

__global__ void k_bnapply(const float* __restrict__ gam, const float* __restrict__ bet) {
    size_t idx = (size_t)blockIdx.x * blockDim.x + threadIdx.x;
    if (idx >= (size_t)NN * HH) return;
    int h = (int)(idx & (HH - 1));
    float m = g_sum[h] * (1.0f / NN);
    float v = g_sumsq[h] * (1.0f / NN) - m * m;
    g_h[idx] = (g_acc[idx] - m) * rsqrtf(v + 1e-5f) * gam[h] + bet[h];
}

__global__ void k_zerostats() {
    int i = threadIdx.x;
    if (i < HH) { g_sum[i] = 0.f; g_sumsq[i] = 0.f; }
}

// ---------------- final: +b4, L2-normalize rows, project 128->3 ----------------
__global__ void k_final(const float* __restrict__ b4, const float* __restrict__ Wm,
                        const float* __restrict__ bm, float* __restrict__ out) {
    __shared__ float wm[HH * 3];
    __shared__ float bb[HH];
    __shared__ float bmv[3];
    for (int i = threadIdx.x; i < HH * 3; i += blockDim.x) wm[i] = Wm[i];
    if (threadIdx.x < HH) bb[threadIdx.x] = b4[threadIdx.x];
    if (threadIdx.x < 3) bmv[threadIdx.x] = bm[threadIdx.x];
    __syncthreads();
    int gw = (blockIdx.x * blockDim.x + threadIdx.x) >> 5;
    int lane = threadIdx.x & 31;
    if (gw >= NN) return;
    float4 v = *(const float4*)&g_acc[(size_t)gw * HH + lane * 4];
    v.x += bb[lane * 4 + 0]; v.y += bb[lane * 4 + 1];
    v.z += bb[lane * 4 + 2]; v.w += bb[lane * 4 + 3];
    float sq = v.x * v.x + v.y * v.y + v.z * v.z + v.w * v.w;
    #pragma unroll
    for (int off = 16; off; off >>= 1) sq += __shfl_xor_sync(0xFFFFFFFFu, sq, off);
    float nrm = sqrtf(sq);
    float inv = 1.0f / fmaxf(nrm, 1e-12f);
    v.x *= inv; v.y *= inv; v.z *= inv; v.w *= inv;
    float o0 = 0.f, o1 = 0.f, o2 = 0.f;
    float vv[4] = {v.x, v.y, v.z, v.w};
    #pragma unroll
    for (int t = 0; t < 4; t++) {
        int h = lane * 4 + t;
        o0 += vv[t] * wm[h * 3 + 0];
        o1 += vv[t] * wm[h * 3 + 1];
        o2 += vv[t] * wm[h * 3 + 2];
    }
    #pragma unroll
    for (int off = 16; off; off >>= 1) {
        o0 += __shfl_xor_sync(0xFFFFFFFFu, o0, off);
        o1 += __shfl_xor_sync(0xFFFFFFFFu, o1, off);
        o2 += __shfl_xor_sync(0xFFFFFFFFu, o2, off);
    }
    if (lane == 0) {
        out[gw * 3 + 0] = o0 + bmv[0];
        out[gw * 3 + 1] = o1 + bmv[1];
        out[gw * 3 + 2] = o2 + bmv[2];
    }
}

// ---------------- host ----------------
static inline int GB(long long n, int b) { return (int)((n + b - 1) / b); }

extern "C" void kernel_launch(void* const* d_in, const int* in_sizes, int n_in,
                              void* d_out, int out_size) {
    const float* x   = (const float*)d_in[0];
    const int*   ei  = (const int*)  d_in[1];
    const float* W1  = (const float*)d_in[2];  const float* b1  = (const float*)d_in[3];
    const float* W2  = (const float*)d_in[4];  const float* b2  = (const float*)d_in[5];
    const float* W3  = (const float*)d_in[6];  const float* b3  = (const float*)d_in[7];
    const float* W4  = (const float*)d_in[8];  const float* b4  = (const float*)d_in[9];
    const float* gm1 = (const float*)d_in[10]; const float* be1 = (const float*)d_in[11];
    const float* gm2 = (const float*)d_in[12]; const float* be2 = (const float*)d_in[13];
    const float* gm3 = (const float*)d_in[14]; const float* be3 = (const float*)d_in[15];
    const float* Wm  = (const float*)d_in[16]; const float* bm  = (const float*)d_in[17];
    float* out = (float*)d_out;

    float *p_h, *p_T1, *p_T2, *p_T3, *p_acc, *p_q1, *p_q2, *p_q3;
    cudaGetSymbolAddress((void**)&p_h,   g_h);
    cudaGetSymbolAddress((void**)&p_T1,  g_T1);
    cudaGetSymbolAddress((void**)&p_T2,  g_T2);
    cudaGetSymbolAddress((void**)&p_T3,  g_T3);
    cudaGetSymbolAddress((void**)&p_acc, g_acc);
    cudaGetSymbolAddress((void**)&p_q1,  g_q1);
    cudaGetSymbolAddress((void**)&p_q2,  g_q2);
    cudaGetSymbolAddress((void**)&p_q3,  g_q3);

    // --- graph setup ---
    k_zero   <<<GB(NN, 256), 256>>>();
    k_degree <<<GB(EE, 256), 256>>>(ei);
    k_dinv   <<<GB(NN, 256), 256>>>();
    k_scan   <<<1, 1024>>>();
    k_scatter<<<GB(EE, 256), 256>>>(ei);

    // --- layer 1 (3 -> 128), leaky_relu + BN ---
    k_prop3<<<GB(NN, 256), 256>>>(x,    x,    p_q1, 1.f,  0.f);
    k_prop3<<<GB(NN, 256), 256>>>(p_q1, x,    p_q2, 2.f, -1.f);
    k_prop3<<<GB(NN, 256), 256>>>(p_q2, p_q1, p_q3, 2.f, -1.f);
    k_layer1<<<GB(NN, L1_ROWS), 128>>>(x, W1, b1);
    k_bnapply<<<GB((long long)NN * HH, 256), 256>>>(gm1, be1);
    k_zerostats<<<1, 128>>>();

    const int propBlocks = GB((long long)NN * 32, 256);
    const int gemmBlocks = GB(NN, BM);
    const int statBlocks = GB(NN, AS_ROWS);
    const int bnBlocks   = GB((long long)NN * HH, 256);

    // --- layer 2 (128 -> 128), leaky_relu + BN ---
    k_prop128<<<propBlocks, 256>>>(p_h,  p_h,  p_T1, 1.f,  0.f);
    k_prop128<<<propBlocks, 256>>>(p_T1, p_h,  p_T2, 2.f, -1.f);
    k_prop128<<<propBlocks, 256>>>(p_T2, p_T1, p_T3, 2.f, -1.f);
    k_gemm4<<<gemmBlocks, 256>>>(p_h, p_T1, p_T2, p_T3, W2, p_acc, b2, 0.01f);
    k_stats<<<statBlocks, 128>>>();
    k_bnapply<<<bnBlocks, 256>>>(gm2, be2);
    k_zerostats<<<1, 128>>>();

    // --- layer 3 (128 -> 128), relu + BN ---
    k_prop128<<<propBlocks, 256>>>(p_h,  p_h,  p_T1, 1.f,  0.f);
    k_prop128<<<propBlocks, 256>>>(p_T1, p_h,  p_T2, 2.f, -1.f);
    k_prop128<<<propBlocks, 256>>>(p_T2, p_T1, p_T3, 2.f, -1.f);
    k_gemm4<<<gemmBlocks, 256>>>(p_h, p_T1, p_T2, p_T3, W3, p_acc, b3, 0.0f);
    k_stats<<<statBlocks, 128>>>();
    k_bnapply<<<bnBlocks, 256>>>(gm3, be3);

    // --- layer 4 (128 -> 128), then normalize + project ---
    k_prop128<<<propBlocks, 256>>>(p_h,  p_h,  p_T1, 1.f,  0.f);
    k_prop128<<<propBlocks, 256>>>(p_T1, p_h,  p_T2, 2.f, -1.f);
    k_prop128<<<propBlocks, 256>>>(p_T2, p_T1, p_T3, 2.f, -1.f);
    k_gemm4<<<gemmBlocks, 256>>>(p_h, p_T1, p_T2, p_T3, W4, p_acc, (const float*)nullptr, 0.0f);
    k_final<<<GB((long long)NN * 32, 256), 256>>>(b4, Wm, bm, out);
}

// round 8
// speedup vs baseline: 1.5005x; 1.5005x over previous
#include <cuda_runtime.h>
#include <cuda_bf16.h>
#include <math.h>
#include <stdint.h>

#define NN 50000
#define EE 800000
#define HH 128

// ================= scratch (static device globals; no allocation) =================
__device__ float g_deg[NN];
__device__ int   g_indeg[NN];
__device__ int   g_rowptr[NN + 1];
__device__ int   g_cursor[NN];
__device__ int   g_col[EE];
__device__ float g_wgt[EE];

__device__ float g_h  [(size_t)NN * HH];
__device__ float g_T1 [(size_t)NN * HH];
__device__ float g_T2 [(size_t)NN * HH];
__device__ float g_T3 [(size_t)NN * HH];
__device__ float g_acc[(size_t)NN * HH];

__device__ float g_q1[NN * 3], g_q2[NN * 3], g_q3[NN * 3];
__device__ float g_sum[HH], g_sumsq[HH];

// pre-converted bf16 hi/lo weights, padded [n][k] layout:
// per layer: 4 terms x { hi[128][136], lo[128][136] }  (17408 bf16 per half)
#define WK_STRIDE 136
#define W_HALF    (HH * WK_STRIDE)            // 17408 bf16
#define W_TERM    (2 * W_HALF)                // 34816 bf16
#define W_LAYER   (4 * W_TERM)                // 139264 bf16
__device__ __nv_bfloat16 g_Wc[3 * W_LAYER];

#define SCB 512
#define NSCB ((NN + SCB - 1) / SCB)
__device__ int g_bsum[NSCB];

// ================= mma.sync helper (sm_80+ HMMA, valid on plain sm_103) ==========
__device__ __forceinline__ void mma16816(float* c, const uint32_t* a,
                                         uint32_t b0, uint32_t b1) {
    asm volatile(
        "mma.sync.aligned.m16n8k16.row.col.f32.bf16.bf16.f32 "
        "{%0,%1,%2,%3}, {%4,%5,%6,%7}, {%8,%9}, {%0,%1,%2,%3};\n"
        : "+f"(c[0]), "+f"(c[1]), "+f"(c[2]), "+f"(c[3])
        : "r"(a[0]), "r"(a[1]), "r"(a[2]), "r"(a[3]), "r"(b0), "r"(b1));
}

// ================= setup kernels =================
__global__ void k_zero() {
    int i = blockIdx.x * blockDim.x + threadIdx.x;
    if (i < NN) { g_deg[i] = 0.f; g_indeg[i] = 0; }
    if (i < HH) { g_sum[i] = 0.f; g_sumsq[i] = 0.f; }
}

__global__ void k_degree(const int* __restrict__ ei) {
    int e = blockIdx.x * blockDim.x + threadIdx.x;
    if (e >= EE) return;
    atomicAdd(&g_deg[ei[e]], 1.0f);
    atomicAdd(&g_indeg[ei[EE + e]], 1);
}

__global__ void k_dinv() {
    int i = blockIdx.x * blockDim.x + threadIdx.x;
    if (i >= NN) return;
    float d = g_deg[i];
    g_deg[i] = (d > 0.f) ? rsqrtf(d) : 0.f;
}

// ---- block-parallel exclusive scan of indeg -> rowptr ----
__global__ void k_bsum() {
    __shared__ int sh[SCB];
    int i = blockIdx.x * SCB + threadIdx.x;
    sh[threadIdx.x] = (i < NN) ? g_indeg[i] : 0;
    __syncthreads();
    for (int off = SCB / 2; off > 0; off >>= 1) {
        if (threadIdx.x < off) sh[threadIdx.x] += sh[threadIdx.x + off];
        __syncthreads();
    }
    if (threadIdx.x == 0) g_bsum[blockIdx.x] = sh[0];
}
__global__ void k_bscan() {
    int acc = 0;
    for (int i = 0; i < NSCB; i++) { int v = g_bsum[i]; g_bsum[i] = acc; acc += v; }
    g_rowptr[NN] = acc;
}
__global__ void k_scanfin() {
    __shared__ int sh[SCB];
    int t = threadIdx.x;
    int i = blockIdx.x * SCB + t;
    int v = (i < NN) ? g_indeg[i] : 0;
    sh[t] = v;
    __syncthreads();
    for (int off = 1; off < SCB; off <<= 1) {
        int add = (t >= off) ? sh[t - off] : 0;
        __syncthreads();
        sh[t] += add;
        __syncthreads();
    }
    if (i < NN) {
        int ex = g_bsum[blockIdx.x] + sh[t] - v;
        g_rowptr[i] = ex;
        g_cursor[i] = ex;
    }
}

__global__ void k_scatter(const int* __restrict__ ei) {
    int e = blockIdx.x * blockDim.x + threadIdx.x;
    if (e >= EE) return;
    int s = ei[e];
    int d = ei[EE + e];
    float w = -g_deg[s] * g_deg[d];
    int pos = atomicAdd(&g_cursor[d], 1);
    g_col[pos] = s;
    g_wgt[pos] = w;
}

// ---- W conversion: fp32 W[t][k][n] -> bf16 hi/lo [t][n][k] (stride 136) ----
__global__ void k_wconv(const float* __restrict__ W, __nv_bfloat16* __restrict__ dst) {
    int idx = blockIdx.x * blockDim.x + threadIdx.x;
    if (idx >= 4 * 16384) return;
    int t = idx >> 14;
    int rem = idx & 16383;
    int n = rem >> 7;
    int k = rem & 127;
    float v = W[(t << 14) + (k << 7) + n];
    __nv_bfloat16 hi = __float2bfloat16(v);
    __nv_bfloat16 lo = __float2bfloat16(v - __bfloat162float(hi));
    __nv_bfloat16* base = dst + (size_t)t * W_TERM + n * WK_STRIDE + k;
    base[0] = hi;
    base[W_HALF] = lo;
}

// ================= propagation =================
__global__ void k_prop128(const float* __restrict__ t, const float* __restrict__ sub,
                          float* __restrict__ out, float scale, float beta) {
    int gw = (blockIdx.x * blockDim.x + threadIdx.x) >> 5;
    int lane = threadIdx.x & 31;
    if (gw >= NN) return;
    int beg = g_rowptr[gw], end = g_rowptr[gw + 1];
    float ax = 0.f, ay = 0.f, az = 0.f, aw = 0.f;
    for (int e = beg; e < end; e++) {
        int s = __ldg(&g_col[e]);
        float w = __ldg(&g_wgt[e]);
        float4 v = *(const float4*)&t[(size_t)s * HH + lane * 4];
        ax += w * v.x; ay += w * v.y; az += w * v.z; aw += w * v.w;
    }
    float4 r;
    if (beta != 0.f) {
        float4 sv = *(const float4*)&sub[(size_t)gw * HH + lane * 4];
        r.x = scale * ax + beta * sv.x;
        r.y = scale * ay + beta * sv.y;
        r.z = scale * az + beta * sv.z;
        r.w = scale * aw + beta * sv.w;
    } else {
        r.x = scale * ax; r.y = scale * ay; r.z = scale * az; r.w = scale * aw;
    }
    *(float4*)&out[(size_t)gw * HH + lane * 4] = r;
}

__global__ void k_prop3(const float* __restrict__ t, const float* __restrict__ sub,
                        float* __restrict__ out, float scale, float beta) {
    int i = blockIdx.x * blockDim.x + threadIdx.x;
    if (i >= NN) return;
    int beg = g_rowptr[i], end = g_rowptr[i + 1];
    float a0 = 0.f, a1 = 0.f, a2 = 0.f;
    for (int e = beg; e < end; e++) {
        int s = g_col[e];
        float w = g_wgt[e];
        a0 += w * t[s * 3 + 0];
        a1 += w * t[s * 3 + 1];
        a2 += w * t[s * 3 + 2];
    }
    if (beta != 0.f) {
        out[i * 3 + 0] = scale * a0 + beta * sub[i * 3 + 0];
        out[i * 3 + 1] = scale * a1 + beta * sub[i * 3 + 1];
        out[i * 3 + 2] = scale * a2 + beta * sub[i * 3 + 2];
    } else {
        out[i * 3 + 0] = scale * a0;
        out[i * 3 + 1] = scale * a1;
        out[i * 3 + 2] = scale * a2;
    }
}

// ================= layer 1 (3->128) SIMT =================
#define L1_ROWS 64
__global__ void k_layer1(const float* __restrict__ x,
                         const float* __restrict__ W1, const float* __restrict__ b1) {
    __shared__ float w[4 * 3 * HH];
    __shared__ float bb[HH];
    for (int i = threadIdx.x; i < 4 * 3 * HH; i += blockDim.x) w[i] = W1[i];
    if (threadIdx.x < HH) bb[threadIdx.x] = b1[threadIdx.x];
    __syncthreads();
    int h = threadIdx.x;
    int row0 = blockIdx.x * L1_ROWS;
    float s = 0.f, sq = 0.f;
    for (int r = 0; r < L1_ROWS; r++) {
        int i = row0 + r;
        if (i >= NN) break;
        float acc = bb[h];
        #pragma unroll
        for (int c = 0; c < 3; c++) {
            acc += x[i * 3 + c]    * w[(0 * 3 + c) * HH + h];
            acc += g_q1[i * 3 + c] * w[(1 * 3 + c) * HH + h];
            acc += g_q2[i * 3 + c] * w[(2 * 3 + c) * HH + h];
            acc += g_q3[i * 3 + c] * w[(3 * 3 + c) * HH + h];
        }
        float y = (acc > 0.f) ? acc : 0.01f * acc;
        g_acc[(size_t)i * HH + h] = y;
        s += y; sq += y * y;
    }
    atomicAdd(&g_sum[h], s);
    atomicAdd(&g_sumsq[h], sq);
}

// ================= mma.sync split-bf16 4-term GEMM =================
// C[128-tile,128] = sum_t Ts[t] @ W[t]  via (Ahi*Bhi + Ahi*Blo + Alo*Bhi)
// SMEM bf16 buffers (row stride 136): A_hi, A_lo (row-major [m][k]),
//                                     B_hi, B_lo ([n][k]).
#define SM_AHI 0
#define SM_ALO (SM_AHI + W_HALF)
#define SM_BHI (SM_ALO + W_HALF)
#define SM_BLO (SM_BHI + W_HALF)
#define SMEM_BF ((size_t)(SM_BLO + W_HALF))            // 69632 bf16
#define SMEM_BYTES (SMEM_BF * 2)                       // 139264 bytes

__global__ void __launch_bounds__(256, 1)
k_mgemm(const float* __restrict__ T0, const float* __restrict__ T1,
        const float* __restrict__ T2, const float* __restrict__ T3,
        const __nv_bfloat16* __restrict__ Wc,
        float* __restrict__ C, const float* __restrict__ bias, float slope) {
    extern __shared__ __nv_bfloat16 sm[];
    int tid = threadIdx.x;
    int wid = tid >> 5, lane = tid & 31;
    int gid = lane >> 2, qid = lane & 3;     // mma fragment row-group / quad id
    int wm = wid & 3, wn = wid >> 2;         // warp tile: rows wm*32, cols wn*64
    int row0 = blockIdx.x * 128;

    float acc[2][8][4];
    #pragma unroll
    for (int i = 0; i < 2; i++)
        #pragma unroll
        for (int j = 0; j < 8; j++)
            #pragma unroll
            for (int q = 0; q < 4; q++) acc[i][j][q] = 0.f;

    const float* Ts[4] = {T0, T1, T2, T3};
    for (int t = 0; t < 4; t++) {
        // --- stage A: fp32 -> bf16 hi/lo, [m][k] stride 136 ---
        const float* T = Ts[t];
        for (int q = tid; q < 4096; q += 256) {
            int r = q >> 5;
            int c = (q & 31) << 2;
            int gi = row0 + r;
            float4 v = make_float4(0.f, 0.f, 0.f, 0.f);
            if (gi < NN) v = *(const float4*)&T[(size_t)gi * HH + c];
            __nv_bfloat16 hx = __float2bfloat16(v.x), hy = __float2bfloat16(v.y);
            __nv_bfloat16 hz = __float2bfloat16(v.z), hw = __float2bfloat16(v.w);
            int o = r * WK_STRIDE + c;
            sm[SM_AHI + o + 0] = hx; sm[SM_AHI + o + 1] = hy;
            sm[SM_AHI + o + 2] = hz; sm[SM_AHI + o + 3] = hw;
            sm[SM_ALO + o + 0] = __float2bfloat16(v.x - __bfloat162float(hx));
            sm[SM_ALO + o + 1] = __float2bfloat16(v.y - __bfloat162float(hy));
            sm[SM_ALO + o + 2] = __float2bfloat16(v.z - __bfloat162float(hz));
            sm[SM_ALO + o + 3] = __float2bfloat16(v.w - __bfloat162float(hw));
        }
        // --- stage B: linear copy of pre-converted hi+lo (69632 B contiguous) ---
        {
            const int4* src = (const int4*)(Wc + (size_t)t * W_TERM);
            int4* dst = (int4*)(sm + SM_BHI);
            for (int q = tid; q < (2 * W_HALF * 2) / 16; q += 256) dst[q] = src[q];
        }
        __syncthreads();

        // --- compute: 3 passes (hi*hi, hi*lo, lo*hi) ---
        #pragma unroll
        for (int pass = 0; pass < 3; pass++) {
            const __nv_bfloat16* Ab = sm + ((pass == 2) ? SM_ALO : SM_AHI);
            const __nv_bfloat16* Bb = sm + ((pass == 1) ? SM_BLO : SM_BHI);
            #pragma unroll
            for (int ks = 0; ks < 8; ks++) {
                int k0 = ks * 16;
                uint32_t a[2][4];
                #pragma unroll
                for (int mt = 0; mt < 2; mt++) {
                    int r = wm * 32 + mt * 16 + gid;
                    a[mt][0] = *(const uint32_t*)&Ab[(r    ) * WK_STRIDE + k0     + qid * 2];
                    a[mt][1] = *(const uint32_t*)&Ab[(r + 8) * WK_STRIDE + k0     + qid * 2];
                    a[mt][2] = *(const uint32_t*)&Ab[(r    ) * WK_STRIDE + k0 + 8 + qid * 2];
                    a[mt][3] = *(const uint32_t*)&Ab[(r + 8) * WK_STRIDE + k0 + 8 + qid * 2];
                }
                #pragma unroll
                for (int nt = 0; nt < 8; nt++) {
                    int n = wn * 64 + nt * 8 + gid;
                    uint32_t b0 = *(const uint32_t*)&Bb[n * WK_STRIDE + k0     + qid * 2];
                    uint32_t b1 = *(const uint32_t*)&Bb[n * WK_STRIDE + k0 + 8 + qid * 2];
                    mma16816(acc[0][nt], a[0], b0, b1);
                    mma16816(acc[1][nt], a[1], b0, b1);
                }
            }
        }
        __syncthreads();
    }

    // --- epilogue: bias + activation (if bias), store fp32 ---
    #pragma unroll
    for (int mt = 0; mt < 2; mt++) {
        int r0 = row0 + wm * 32 + mt * 16 + gid;
        #pragma unroll
        for (int nt = 0; nt < 8; nt++) {
            int col = wn * 64 + nt * 8 + qid * 2;
            float c0 = acc[mt][nt][0], c1 = acc[mt][nt][1];
            float c2 = acc[mt][nt][2], c3 = acc[mt][nt][3];
            if (bias) {
                float bv0 = bias[col], bv1 = bias[col + 1];
                c0 += bv0; c0 = (c0 > 0.f) ? c0 : slope * c0;
                c1 += bv1; c1 = (c1 > 0.f) ? c1 : slope * c1;
                c2 += bv0; c2 = (c2 > 0.f) ? c2 : slope * c2;
                c3 += bv1; c3 = (c3 > 0.f) ? c3 : slope * c3;
            }
            if (r0 < NN)     *(float2*)&C[(size_t)r0 * HH + col]       = make_float2(c0, c1);
            if (r0 + 8 < NN) *(float2*)&C[(size_t)(r0 + 8) * HH + col] = make_float2(c2, c3);
        }
    }
}

// ================= BN stats / apply =================
#define AS_ROWS 256
__global__ void k_stats() {
    int h = threadIdx.x;
    int row0 = blockIdx.x * AS_ROWS;
    float s = 0.f, sq = 0.f;
    for (int r = 0; r < AS_ROWS; r++) {
        int i = row0 + r;
        if (i >= NN) break;
        float v = g_acc[(size_t)i * HH + h];
        s += v; sq += v * v;
    }
    atomicAdd(&g_sum[h], s);
    atomicAdd(&g_sumsq[h], sq);
}

__global__ void k_bnapply(const float* __restrict__ gam, const float* __restrict__ bet) {
    size_t idx = (size_t)blockIdx.x * blockDim.x + threadIdx.x;
    if (idx >= (size_t)NN * HH) return;
    int h = (int)(idx & (HH - 1));
    float m = g_sum[h] * (1.0f / NN);
    float v = g_sumsq[h] * (1.0f / NN) - m * m;
    g_h[idx] = (g_acc[idx] - m) * rsqrtf(v + 1e-5f) * gam[h] + bet[h];
}

__global__ void k_zerostats() {
    int i = threadIdx.x;
    if (i < HH) { g_sum[i] = 0.f; g_sumsq[i] = 0.f; }
}

// ================= final: +b4, L2-normalize, project 128->3 =================
__global__ void k_final(const float* __restrict__ b4, const float* __restrict__ Wm,
                        const float* __restrict__ bm, float* __restrict__ out) {
    __shared__ float wm[HH * 3];
    __shared__ float bb[HH];
    __shared__ float bmv[3];
    for (int i = threadIdx.x; i < HH * 3; i += blockDim.x) wm[i] = Wm[i];
    if (threadIdx.x < HH) bb[threadIdx.x] = b4[threadIdx.x];
    if (threadIdx.x < 3) bmv[threadIdx.x] = bm[threadIdx.x];
    __syncthreads();
    int gw = (blockIdx.x * blockDim.x + threadIdx.x) >> 5;
    int lane = threadIdx.x & 31;
    if (gw >= NN) return;
    float4 v = *(const float4*)&g_acc[(size_t)gw * HH + lane * 4];
    v.x += bb[lane * 4 + 0]; v.y += bb[lane * 4 + 1];
    v.z += bb[lane * 4 + 2]; v.w += bb[lane * 4 + 3];
    float sq = v.x * v.x + v.y * v.y + v.z * v.z + v.w * v.w;
    #pragma unroll
    for (int off = 16; off; off >>= 1) sq += __shfl_xor_sync(0xFFFFFFFFu, sq, off);
    float inv = 1.0f / fmaxf(sqrtf(sq), 1e-12f);
    v.x *= inv; v.y *= inv; v.z *= inv; v.w *= inv;
    float o0 = 0.f, o1 = 0.f, o2 = 0.f;
    float vv[4] = {v.x, v.y, v.z, v.w};
    #pragma unroll
    for (int t = 0; t < 4; t++) {
        int h = lane * 4 + t;
        o0 += vv[t] * wm[h * 3 + 0];
        o1 += vv[t] * wm[h * 3 + 1];
        o2 += vv[t] * wm[h * 3 + 2];
    }
    #pragma unroll
    for (int off = 16; off; off >>= 1) {
        o0 += __shfl_xor_sync(0xFFFFFFFFu, o0, off);
        o1 += __shfl_xor_sync(0xFFFFFFFFu, o1, off);
        o2 += __shfl_xor_sync(0xFFFFFFFFu, o2, off);
    }
    if (lane == 0) {
        out[gw * 3 + 0] = o0 + bmv[0];
        out[gw * 3 + 1] = o1 + bmv[1];
        out[gw * 3 + 2] = o2 + bmv[2];
    }
}

// ================= host =================
static inline int GB(long long n, int b) { return (int)((n + b - 1) / b); }

extern "C" void kernel_launch(void* const* d_in, const int* in_sizes, int n_in,
                              void* d_out, int out_size) {
    const float* x   = (const float*)d_in[0];
    const int*   ei  = (const int*)  d_in[1];
    const float* W1  = (const float*)d_in[2];  const float* b1  = (const float*)d_in[3];
    const float* W2  = (const float*)d_in[4];  const float* b2  = (const float*)d_in[5];
    const float* W3  = (const float*)d_in[6];  const float* b3  = (const float*)d_in[7];
    const float* W4  = (const float*)d_in[8];  const float* b4  = (const float*)d_in[9];
    const float* gm1 = (const float*)d_in[10]; const float* be1 = (const float*)d_in[11];
    const float* gm2 = (const float*)d_in[12]; const float* be2 = (const float*)d_in[13];
    const float* gm3 = (const float*)d_in[14]; const float* be3 = (const float*)d_in[15];
    const float* Wm  = (const float*)d_in[16]; const float* bm  = (const float*)d_in[17];
    float* out = (float*)d_out;

    float *p_h, *p_T1, *p_T2, *p_T3, *p_acc, *p_q1, *p_q2, *p_q3;
    __nv_bfloat16* p_Wc;
    cudaGetSymbolAddress((void**)&p_h,   g_h);
    cudaGetSymbolAddress((void**)&p_T1,  g_T1);
    cudaGetSymbolAddress((void**)&p_T2,  g_T2);
    cudaGetSymbolAddress((void**)&p_T3,  g_T3);
    cudaGetSymbolAddress((void**)&p_acc, g_acc);
    cudaGetSymbolAddress((void**)&p_q1,  g_q1);
    cudaGetSymbolAddress((void**)&p_q2,  g_q2);
    cudaGetSymbolAddress((void**)&p_q3,  g_q3);
    cudaGetSymbolAddress((void**)&p_Wc,  g_Wc);

    cudaFuncSetAttribute(k_mgemm, cudaFuncAttributeMaxDynamicSharedMemorySize,
                         (int)SMEM_BYTES);

    // --- graph setup ---
    k_zero   <<<GB(NN, 256), 256>>>();
    k_degree <<<GB(EE, 256), 256>>>(ei);
    k_dinv   <<<GB(NN, 256), 256>>>();
    k_bsum   <<<NSCB, SCB>>>();
    k_bscan  <<<1, 1>>>();
    k_scanfin<<<NSCB, SCB>>>();
    k_scatter<<<GB(EE, 256), 256>>>(ei);
    k_wconv  <<<GB(4 * 16384, 256), 256>>>(W2, p_Wc);
    k_wconv  <<<GB(4 * 16384, 256), 256>>>(W3, p_Wc + W_LAYER);
    k_wconv  <<<GB(4 * 16384, 256), 256>>>(W4, p_Wc + 2 * W_LAYER);

    // --- layer 1 (3 -> 128), leaky_relu + BN ---
    k_prop3<<<GB(NN, 256), 256>>>(x,    x,    p_q1, 1.f,  0.f);
    k_prop3<<<GB(NN, 256), 256>>>(p_q1, x,    p_q2, 2.f, -1.f);
    k_prop3<<<GB(NN, 256), 256>>>(p_q2, p_q1, p_q3, 2.f, -1.f);
    k_layer1<<<GB(NN, L1_ROWS), 128>>>(x, W1, b1);
    k_bnapply<<<GB((long long)NN * HH, 256), 256>>>(gm1, be1);
    k_zerostats<<<1, 128>>>();

    const int propBlocks = GB((long long)NN * 32, 256);
    const int gemmBlocks = GB(NN, 128);
    const int statBlocks = GB(NN, AS_ROWS);
    const int bnBlocks   = GB((long long)NN * HH, 256);

    // --- layer 2 (128 -> 128), leaky_relu + BN ---
    k_prop128<<<propBlocks, 256>>>(p_h,  p_h,  p_T1, 1.f,  0.f);
    k_prop128<<<propBlocks, 256>>>(p_T1, p_h,  p_T2, 2.f, -1.f);
    k_prop128<<<propBlocks, 256>>>(p_T2, p_T1, p_T3, 2.f, -1.f);
    k_mgemm<<<gemmBlocks, 256, SMEM_BYTES>>>(p_h, p_T1, p_T2, p_T3, p_Wc, p_acc, b2, 0.01f);
    k_stats<<<statBlocks, 128>>>();
    k_bnapply<<<bnBlocks, 256>>>(gm2, be2);
    k_zerostats<<<1, 128>>>();

    // --- layer 3 (128 -> 128), relu + BN ---
    k_prop128<<<propBlocks, 256>>>(p_h,  p_h,  p_T1, 1.f,  0.f);
    k_prop128<<<propBlocks, 256>>>(p_T1, p_h,  p_T2, 2.f, -1.f);
    k_prop128<<<propBlocks, 256>>>(p_T2, p_T1, p_T3, 2.f, -1.f);
    k_mgemm<<<gemmBlocks, 256, SMEM_BYTES>>>(p_h, p_T1, p_T2, p_T3, p_Wc + W_LAYER, p_acc, b3, 0.0f);
    k_stats<<<statBlocks, 128>>>();
    k_bnapply<<<bnBlocks, 256>>>(gm3, be3);

    // --- layer 4 (128 -> 128), then normalize + project ---
    k_prop128<<<propBlocks, 256>>>(p_h,  p_h,  p_T1, 1.f,  0.f);
    k_prop128<<<propBlocks, 256>>>(p_T1, p_h,  p_T2, 2.f, -1.f);
    k_prop128<<<propBlocks, 256>>>(p_T2, p_T1, p_T3, 2.f, -1.f);
    k_mgemm<<<gemmBlocks, 256, SMEM_BYTES>>>(p_h, p_T1, p_T2, p_T3, p_Wc + 2 * W_LAYER, p_acc,
                                             (const float*)nullptr, 0.0f);
    k_final<<<GB((long long)NN * 32, 256), 256>>>(b4, Wm, bm, out);
}